// round 13
// baseline (speedup 1.0000x reference)
#include <cuda_runtime.h>
#include <cuda_fp16.h>

#define NN 100000
#define NE 1600000
#define NG 2048
#define HID 64
#define INF 14
#define EPSV 1e-5f
#define SCAN_B 1024
#define SCAN_NB ((NN + SCAN_B - 1) / SCAN_B)   // 98

// ---------------- scratch (device globals; no allocation allowed) -----------
__device__ __half2 g_Ah[NN * 32];      // 12.8 MB xw buffer (fp16)
__device__ float   g_B[NN * HID];      // 25.6 MB h buffer (fp32)
__device__ float   g_dinv[NN];
__device__ float   g_stats[3][2 * HID];
__device__ int2    g_edge[NE];         // CSR-sorted (row, norm-bits)
__device__ int     g_cnt[NN];
__device__ int     g_off[NN + 1];
__device__ int     g_cur[NN];
__device__ int     g_bsum[SCAN_NB];
__device__ int     g_batch[NN];
__device__ int     g_is64;

// ---------------- init: zero + dtype detection -------------------------------
__global__ void init_k(const int* __restrict__ ei32) {
    int i = blockIdx.x * blockDim.x + threadIdx.x;
    if (i < NN) { g_cnt[i] = 0; g_dinv[i] = 0.f; }
    if (i < 3 * 2 * HID) ((float*)g_stats)[i] = 0.f;
    if (i == 0) g_off[NN] = NE;
    if (blockIdx.x == 0) {
        __shared__ int any;
        if (threadIdx.x == 0) any = 0;
        __syncthreads();
        for (int s = 0; s < 8; s++) {
            long idx = 1 + 2L * (threadIdx.x * 8 + s) * 780;
            if (idx < 2L * NE && ei32[idx] != 0) any = 1;
        }
        __syncthreads();
        if (threadIdx.x == 0) g_is64 = (any == 0) ? 1 : 0;
    }
}

// histogram (count + weighted degree) + batch conversion
__global__ void convert_hist_k(const void* __restrict__ ei, const void* __restrict__ bt,
                               const float* __restrict__ w) {
    long t0 = (long)blockIdx.x * blockDim.x + threadIdx.x;
    long stride = (long)gridDim.x * blockDim.x;
    if (g_is64) {
        const long long* e = (const long long*)ei;
        const long long* b = (const long long*)bt;
        for (long i = t0; i < NE; i += stride) {
            int c = (int)e[NE + i];
            atomicAdd(&g_cnt[c], 1);
            atomicAdd(&g_dinv[c], w[i]);
        }
        for (long i = t0; i < NN; i += stride) g_batch[i] = (int)b[i];
    } else {
        const int* e = (const int*)ei;
        const int* b = (const int*)bt;
        for (long i = t0; i < NE; i += stride) {
            int c = e[NE + i];
            atomicAdd(&g_cnt[c], 1);
            atomicAdd(&g_dinv[c], w[i]);
        }
        for (long i = t0; i < NN; i += stride) g_batch[i] = b[i];
    }
}

// ---------------- scan pass 1 (block sums) + fused dinv ----------------------
__global__ void scan1_k() {
    __shared__ int sh[256];
    int base = blockIdx.x * SCAN_B;
    int s = 0;
    for (int i = threadIdx.x; i < SCAN_B; i += 256) {
        int idx = base + i;
        if (idx < NN) {
            s += g_cnt[idx];
            g_dinv[idx] = rsqrtf(g_dinv[idx] + 1.f);
        }
    }
    sh[threadIdx.x] = s;
    __syncthreads();
    for (int o = 128; o > 0; o >>= 1) {
        if (threadIdx.x < o) sh[threadIdx.x] += sh[threadIdx.x + o];
        __syncthreads();
    }
    if (threadIdx.x == 0) g_bsum[blockIdx.x] = sh[0];
}

// scan pass 2+3 fused
__global__ void scan3_k() {
    __shared__ int bs[128];
    __shared__ int sh[256];
    __shared__ int base_s;
    int tid = threadIdx.x;
    if (tid < 128) bs[tid] = (tid < SCAN_NB) ? g_bsum[tid] : 0;
    __syncthreads();
    for (int o = 1; o < 128; o <<= 1) {
        int v = (tid < 128 && tid >= o) ? bs[tid - o] : 0;
        __syncthreads();
        if (tid < 128) bs[tid] += v;
        __syncthreads();
    }
    if (tid == 0) base_s = bs[blockIdx.x] - g_bsum[blockIdx.x];
    __syncthreads();
    int base = blockIdx.x * SCAN_B;
    int i0 = base + tid * 4;
    int vals[4];
    int tsum = 0;
#pragma unroll
    for (int k = 0; k < 4; k++) {
        int idx = i0 + k;
        vals[k] = (idx < NN) ? g_cnt[idx] : 0;
        tsum += vals[k];
    }
    sh[tid] = tsum;
    __syncthreads();
    for (int o = 1; o < 256; o <<= 1) {
        int v = (tid >= o) ? sh[tid - o] : 0;
        __syncthreads();
        sh[tid] += v;
        __syncthreads();
    }
    int excl = base_s + sh[tid] - tsum;
#pragma unroll
    for (int k = 0; k < 4; k++) {
        int idx = i0 + k;
        if (idx < NN) { g_off[idx] = excl; g_cur[idx] = excl; excl += vals[k]; }
    }
}

// scatter edges into CSR order as packed (row, norm)
__global__ void fill_k(const void* __restrict__ ei, const float* __restrict__ w) {
    long e = (long)blockIdx.x * 256 + threadIdx.x;
    if (e >= NE) return;
    int r, c;
    if (g_is64) {
        const long long* ee = (const long long*)ei;
        r = (int)ee[e]; c = (int)ee[NE + e];
    } else {
        const int* ee = (const int*)ei;
        r = ee[e]; c = ee[NE + e];
    }
    int pos = atomicAdd(&g_cur[c], 1);
    float nrm = g_dinv[r] * w[e] * g_dinv[c];
    g_edge[pos] = make_int2(r, __float_as_int(nrm));
}

// ---------------- layer-1 GEMM: x[N,14] @ W1[14,64] -> fp16 ------------------
__global__ void xw14_k(const float* __restrict__ x, const float* __restrict__ W,
                       __half2* __restrict__ outh) {
    __shared__ float Ws[INF * HID];
    __shared__ float Xs[16][INF];
    int tid = threadIdx.x;  // 256
    for (int i = tid; i < INF * HID; i += 256) Ws[i] = W[i];
    int node0 = blockIdx.x * 16;
    for (int i = tid; i < 16 * INF; i += 256)
        Xs[i / INF][i % INF] = x[(long)(node0 + i / INF) * INF + i % INF];
    __syncthreads();
    int o = tid & 63, ng = tid >> 6;     // 4 groups x 4 nodes
    float acc[4] = {0.f, 0.f, 0.f, 0.f};
#pragma unroll
    for (int k = 0; k < INF; k++) {
        float w = Ws[k * HID + o];
#pragma unroll
        for (int i = 0; i < 4; i++) acc[i] = fmaf(Xs[ng * 4 + i][k], w, acc[i]);
    }
#pragma unroll
    for (int i = 0; i < 4; i++) {
        float hi = __shfl_down_sync(0xffffffffu, acc[i], 1);
        if ((o & 1) == 0)
            outh[(long)(node0 + ng * 4 + i) * 32 + (o >> 1)] = __floats2half2_rn(acc[i], hi);
    }
}

// ------ hidden GEMM: act(h)[N,64] @ W[64,64] -> fp16, BN+ReLU fused in ------
__global__ void xw64_k(const float* __restrict__ x, const float* __restrict__ W,
                       __half2* __restrict__ outh, const float* __restrict__ stats,
                       const float* __restrict__ g, const float* __restrict__ bt) {
    __shared__ float Ws[HID * HID];      // 16 KB
    __shared__ float4 Xs[32][16];        // 8 KB
    __shared__ float As[HID], Cs[HID];
    int tid = threadIdx.x;  // 256
    const float4* W4 = (const float4*)W;
    float4* Ws4 = (float4*)Ws;
    for (int i = tid; i < HID * HID / 4; i += 256) Ws4[i] = W4[i];
    if (tid < HID) {
        float mean = stats[tid] * (1.f / NN);
        float var = stats[64 + tid] * (1.f / NN) - mean * mean;
        float a = g[tid] * rsqrtf(var + EPSV);
        As[tid] = a;
        Cs[tid] = bt[tid] - mean * a;
    }
    __syncthreads();
    int node0 = blockIdx.x * 32;
    const float4* x4 = (const float4*)x;
    for (int i = tid; i < 32 * 16; i += 256) {
        int n = i >> 4, k4 = i & 15;
        float4 v = x4[(long)(node0 + n) * 16 + k4];
        int f = k4 * 4;
        v.x = fmaxf(fmaf(As[f],     v.x, Cs[f]),     0.f);
        v.y = fmaxf(fmaf(As[f + 1], v.y, Cs[f + 1]), 0.f);
        v.z = fmaxf(fmaf(As[f + 2], v.z, Cs[f + 2]), 0.f);
        v.w = fmaxf(fmaf(As[f + 3], v.w, Cs[f + 3]), 0.f);
        Xs[n][k4] = v;
    }
    __syncthreads();
    int o = tid & 63, ng = tid >> 6;     // 4 groups x 8 nodes
    float acc[8] = {0, 0, 0, 0, 0, 0, 0, 0};
#pragma unroll
    for (int k4 = 0; k4 < 16; k4++) {
        float w0 = Ws[(k4 * 4 + 0) * HID + o];
        float w1 = Ws[(k4 * 4 + 1) * HID + o];
        float w2 = Ws[(k4 * 4 + 2) * HID + o];
        float w3 = Ws[(k4 * 4 + 3) * HID + o];
#pragma unroll
        for (int i = 0; i < 8; i++) {
            float4 xv = Xs[ng * 8 + i][k4];
            acc[i] = fmaf(xv.x, w0, fmaf(xv.y, w1, fmaf(xv.z, w2, fmaf(xv.w, w3, acc[i]))));
        }
    }
#pragma unroll
    for (int i = 0; i < 8; i++) {
        float hi = __shfl_down_sync(0xffffffffu, acc[i], 1);
        if ((o & 1) == 0)
            outh[(long)(node0 + ng * 8 + i) * 32 + (o >> 1)] = __floats2half2_rn(acc[i], hi);
    }
}

// ---- CSR gather: 8 lanes/node, fp16 rows (128B), unroll 4 ------------------
// block 256 = 32 nodes, grid 3125. Nodes rank-sorted by degree inside the
// block so each warp's 4 node-groups have near-equal degree (kills divergence).
// Fused BN-stats accumulation.
__global__ void gatherh_k(const uint4* __restrict__ xw, float* __restrict__ out,
                          const float* __restrict__ b, float* __restrict__ stats) {
    __shared__ float sm[2 * HID];
    __shared__ int s_node[32];
    __shared__ int s_start[32];
    __shared__ int s_end[32];
    int tid = threadIdx.x;  // 256
    if (tid < 2 * HID) sm[tid] = 0.f;
    if (tid < 32) {
        int node = blockIdx.x * 32 + tid;
        int st = g_off[node];
        int en = g_off[node + 1];
        int deg = en - st;
        // rank among the 32 nodes of this block (stable by index)
        int rank = 0;
#pragma unroll
        for (int k = 0; k < 32; k++) {
            int dk = __shfl_sync(0xffffffffu, deg, k);
            rank += (dk < deg) || (dk == deg && k < tid);
        }
        s_node[rank] = node;
        s_start[rank] = st;
        s_end[rank] = en;
    }
    __syncthreads();

    int slot = tid >> 3;
    int q = tid & 7;                       // feats [q*8, q*8+8)
    int node = s_node[slot];
    int start = s_start[slot], end = s_end[slot];
    float d = g_dinv[node];
    float s = d * d;

    float acc[8];
    {
        uint4 sv = xw[(long)node * 8 + q];
        const __half2* h2 = (const __half2*)&sv;
#pragma unroll
        for (int k = 0; k < 4; k++) {
            float2 f = __half22float2(h2[k]);
            acc[2 * k]     = fmaf(s, f.x, b[q * 8 + 2 * k]);
            acc[2 * k + 1] = fmaf(s, f.y, b[q * 8 + 2 * k + 1]);
        }
    }
    int j = start;
    for (; j + 3 < end; j += 4) {
        int2 e0 = g_edge[j], e1 = g_edge[j + 1], e2 = g_edge[j + 2], e3 = g_edge[j + 3];
        uint4 v0 = xw[(long)e0.x * 8 + q];
        uint4 v1 = xw[(long)e1.x * 8 + q];
        uint4 v2 = xw[(long)e2.x * 8 + q];
        uint4 v3 = xw[(long)e3.x * 8 + q];
        float n0 = __int_as_float(e0.y), n1 = __int_as_float(e1.y);
        float n2 = __int_as_float(e2.y), n3 = __int_as_float(e3.y);
        const __half2* a0 = (const __half2*)&v0;
        const __half2* a1 = (const __half2*)&v1;
        const __half2* a2 = (const __half2*)&v2;
        const __half2* a3 = (const __half2*)&v3;
#pragma unroll
        for (int k = 0; k < 4; k++) {
            float2 f0 = __half22float2(a0[k]);
            float2 f1 = __half22float2(a1[k]);
            float2 f2 = __half22float2(a2[k]);
            float2 f3 = __half22float2(a3[k]);
            acc[2 * k]     = fmaf(n0, f0.x, fmaf(n1, f1.x, fmaf(n2, f2.x, fmaf(n3, f3.x, acc[2 * k]))));
            acc[2 * k + 1] = fmaf(n0, f0.y, fmaf(n1, f1.y, fmaf(n2, f2.y, fmaf(n3, f3.y, acc[2 * k + 1]))));
        }
    }
    for (; j < end; j++) {
        int2 e0 = g_edge[j];
        uint4 v0 = xw[(long)e0.x * 8 + q];
        float n0 = __int_as_float(e0.y);
        const __half2* a0 = (const __half2*)&v0;
#pragma unroll
        for (int k = 0; k < 4; k++) {
            float2 f0 = __half22float2(a0[k]);
            acc[2 * k]     = fmaf(n0, f0.x, acc[2 * k]);
            acc[2 * k + 1] = fmaf(n0, f0.y, acc[2 * k + 1]);
        }
    }
    float4* o4 = (float4*)out;
    o4[(long)node * 16 + q * 2]     = make_float4(acc[0], acc[1], acc[2], acc[3]);
    o4[(long)node * 16 + q * 2 + 1] = make_float4(acc[4], acc[5], acc[6], acc[7]);

    // fused BN stats: shfl-reduce across the 4 nodes of this warp, smem, flush
    float ss[8], s2[8];
#pragma unroll
    for (int k = 0; k < 8; k++) { ss[k] = acc[k]; s2[k] = acc[k] * acc[k]; }
#pragma unroll
    for (int off = 8; off < 32; off <<= 1) {
#pragma unroll
        for (int k = 0; k < 8; k++) {
            ss[k] += __shfl_xor_sync(0xffffffffu, ss[k], off);
            s2[k] += __shfl_xor_sync(0xffffffffu, s2[k], off);
        }
    }
    if ((tid & 31) < 8) {
#pragma unroll
        for (int k = 0; k < 8; k++) {
            atomicAdd(&sm[q * 8 + k], ss[k]);
            atomicAdd(&sm[64 + q * 8 + k], s2[k]);
        }
    }
    __syncthreads();
    if (tid < 2 * HID) atomicAdd(&stats[tid], sm[tid]);
}

// ---------------- bn+relu apply -> node_out (streaming, no atomics) ---------
__global__ void bnrelu_node_k(const float4* __restrict__ h, float4* __restrict__ no,
                              const float* __restrict__ stats,
                              const float* __restrict__ g, const float* __restrict__ bt) {
    __shared__ float As[HID], Cs[HID];
    int tid = threadIdx.x;
    if (tid < HID) {
        float mean = stats[tid] * (1.f / NN);
        float var = stats[64 + tid] * (1.f / NN) - mean * mean;
        float a = g[tid] * rsqrtf(var + EPSV);
        As[tid] = a;
        Cs[tid] = bt[tid] - mean * a;
    }
    __syncthreads();
    long t = (long)blockIdx.x * 256 + tid;
    if (t >= (long)NN * 16) return;
    int q = (int)(t & 15);
    int f0 = q * 4;
    float4 v = h[t];
    v.x = fmaxf(fmaf(As[f0],     v.x, Cs[f0]),     0.f);
    v.y = fmaxf(fmaf(As[f0 + 1], v.y, Cs[f0 + 1]), 0.f);
    v.z = fmaxf(fmaf(As[f0 + 2], v.z, Cs[f0 + 2]), 0.f);
    v.w = fmaxf(fmaf(As[f0 + 3], v.w, Cs[f0 + 3]), 0.f);
    no[t] = v;
}

// ---------------- per-graph pooling + FC (sorted batch: binary search) ------
__global__ void poolfc_k(const float* __restrict__ no, float* __restrict__ gemb,
                         const float* __restrict__ W, const float* __restrict__ b,
                         float* __restrict__ out) {
    __shared__ int sb[2];
    __shared__ float red[4];
    int g = blockIdx.x;
    int f = threadIdx.x;  // 64
    if (f < 2) {
        int target = g + f;
        int lo = 0, hi = NN;
        while (lo < hi) {
            int mid = (lo + hi) >> 1;
            if (g_batch[mid] < target) lo = mid + 1; else hi = mid;
        }
        sb[f] = lo;
    }
    __syncthreads();
    int start = sb[0], end = sb[1];
    float acc = 0.f;
    int n = start;
    for (; n + 1 < end; n += 2)
        acc += no[(long)n * HID + f] + no[(long)(n + 1) * HID + f];
    if (n < end) acc += no[(long)n * HID + f];
    gemb[(long)g * HID + f] = acc;

    float p0 = acc * W[f * 2];
    float p1 = acc * W[f * 2 + 1];
#pragma unroll
    for (int o = 16; o > 0; o >>= 1) {
        p0 += __shfl_down_sync(0xffffffffu, p0, o);
        p1 += __shfl_down_sync(0xffffffffu, p1, o);
    }
    if ((f & 31) == 0) { red[(f >> 5) * 2] = p0; red[(f >> 5) * 2 + 1] = p1; }
    __syncthreads();
    if (f == 0) {
        out[g * 2]     = red[0] + red[2] + b[0];
        out[g * 2 + 1] = red[1] + red[3] + b[1];
    }
}

// ---------------- orchestration ----------------------------------------------
extern "C" void kernel_launch(void* const* d_in, const int* in_sizes, int n_in,
                              void* d_out, int out_size) {
    const float* x  = (const float*)d_in[0];
    const void*  ei = d_in[1];
    const void*  bt = d_in[2];
    const float* ew = (const float*)d_in[3];
    const float* W1 = (const float*)d_in[4];
    const float* b1 = (const float*)d_in[5];
    const float* W2 = (const float*)d_in[6];
    const float* b2 = (const float*)d_in[7];
    const float* W3 = (const float*)d_in[8];
    const float* b3 = (const float*)d_in[9];
    const float* g1 = (const float*)d_in[10];
    const float* t1 = (const float*)d_in[11];
    const float* g2 = (const float*)d_in[12];
    const float* t2 = (const float*)d_in[13];
    const float* g3 = (const float*)d_in[14];
    const float* t3 = (const float*)d_in[15];
    const float* fcW = (const float*)d_in[16];
    const float* fcb = (const float*)d_in[17];

    float* out      = (float*)d_out;
    float* node_out = out + NG * 2;
    float* gemb     = node_out + (long)NN * HID;

    __half2* A;
    float *B, *S;
    cudaGetSymbolAddress((void**)&A, g_Ah);
    cudaGetSymbolAddress((void**)&B, g_B);
    cudaGetSymbolAddress((void**)&S, g_stats);

    const int NB_N   = (NN + 255) / 256;                    // 391
    const int NB_E   = (NE + 255) / 256;                    // 6250
    const int NB_NF4 = (int)(((long)NN * 16 + 255) / 256);  // 6250

    // ---- CSR build (once, reused by all 3 layers)
    init_k<<<NB_N, 256>>>((const int*)ei);
    convert_hist_k<<<2048, 256>>>(ei, bt, ew);
    scan1_k<<<SCAN_NB, 256>>>();
    scan3_k<<<SCAN_NB, 256>>>();
    fill_k<<<NB_E, 256>>>(ei, ew);

    // ---- layer 1
    xw14_k<<<NN / 16, 256>>>(x, W1, A);
    gatherh_k<<<NN / 32, 256>>>((const uint4*)A, B, b1, S);

    // ---- layer 2 (BN+ReLU of layer 1 folded into GEMM input)
    xw64_k<<<NN / 32, 256>>>(B, W2, A, S, g1, t1);
    gatherh_k<<<NN / 32, 256>>>((const uint4*)A, B, b2, S + 128);

    // ---- layer 3
    xw64_k<<<NN / 32, 256>>>(B, W3, A, S + 128, g2, t2);
    gatherh_k<<<NN / 32, 256>>>((const uint4*)A, B, b3, S + 256);

    // ---- bn+relu -> node_out, per-graph pool + fc
    bnrelu_node_k<<<NB_NF4, 256>>>((const float4*)B, (float4*)node_out, S + 256, g3, t3);
    poolfc_k<<<NG, 64>>>(node_out, gemb, fcW, fcb, out);
}

// round 15
// speedup vs baseline: 1.0146x; 1.0146x over previous
#include <cuda_runtime.h>
#include <cuda_fp16.h>

#define NN 100000
#define NE 1600000
#define NG 2048
#define HID 64
#define INF 14
#define EPSV 1e-5f
#define SCAN_B 1024
#define SCAN_NB ((NN + SCAN_B - 1) / SCAN_B)   // 98

// ---------------- scratch (device globals; no allocation allowed) -----------
__device__ __half2 g_Ah[NN * 32];      // 12.8 MB xw buffer (fp16)
__device__ float   g_B[NN * HID];      // 25.6 MB h buffer (fp32)
__device__ float   g_dinv[NN];
__device__ float   g_stats[3][2 * HID];
__device__ int2    g_edge[NE];         // CSR-sorted (row, norm-bits)
__device__ int     g_cnt[NN];
__device__ int     g_off[NN + 1];
__device__ int     g_cur[NN];
__device__ int     g_bsum[SCAN_NB];
__device__ int     g_batch[NN];
__device__ int     g_is64;
// monotone flag: 0 (static zero-init) until any edge_weight != 1.0f is seen.
// Never reset -> no init/OR race; deterministic across graph replays since
// inputs are constant.
__device__ int     g_wnot1;

// ---------------- init: zero + dtype detection + weight==1 check -------------
__global__ void init_k(const int* __restrict__ ei32, const float* __restrict__ w) {
    int i = blockIdx.x * blockDim.x + threadIdx.x;
    if (i < NN) { g_cnt[i] = 0; g_dinv[i] = 0.f; }
    if (i < 3 * 2 * HID) ((float*)g_stats)[i] = 0.f;
    if (i == 0) g_off[NN] = NE;
    // exact all-ones check on edge weights (streamed, coalesced)
    int nt = gridDim.x * blockDim.x;
    int bad = 0;
    for (long e = i; e < NE; e += nt)
        if (w[e] != 1.0f) bad = 1;
    if (__syncthreads_or(bad) && threadIdx.x == 0) atomicOr(&g_wnot1, 1);
    if (blockIdx.x == 0) {
        __shared__ int any;
        if (threadIdx.x == 0) any = 0;
        __syncthreads();
        for (int s = 0; s < 8; s++) {
            long idx = 1 + 2L * (threadIdx.x * 8 + s) * 780;
            if (idx < 2L * NE && ei32[idx] != 0) any = 1;
        }
        __syncthreads();
        if (threadIdx.x == 0) g_is64 = (any == 0) ? 1 : 0;
    }
}

// histogram + batch conversion. Fast path: weights all 1 -> only int atomic.
__global__ void convert_hist_k(const void* __restrict__ ei, const void* __restrict__ bt,
                               const float* __restrict__ w) {
    long t0 = (long)blockIdx.x * blockDim.x + threadIdx.x;
    long stride = (long)gridDim.x * blockDim.x;
    bool wgen = (g_wnot1 != 0);
    if (g_is64) {
        const long long* e = (const long long*)ei;
        const long long* b = (const long long*)bt;
        for (long i = t0; i < NE; i += stride) {
            int c = (int)e[NE + i];
            atomicAdd(&g_cnt[c], 1);
            if (wgen) atomicAdd(&g_dinv[c], w[i]);
        }
        for (long i = t0; i < NN; i += stride) g_batch[i] = (int)b[i];
    } else {
        const int* e = (const int*)ei;
        const int* b = (const int*)bt;
        for (long i = t0; i < NE; i += stride) {
            int c = e[NE + i];
            atomicAdd(&g_cnt[c], 1);
            if (wgen) atomicAdd(&g_dinv[c], w[i]);
        }
        for (long i = t0; i < NN; i += stride) g_batch[i] = b[i];
    }
}

// ---------------- scan pass 1 (block sums) + fused dinv ----------------------
__global__ void scan1_k() {
    __shared__ int sh[256];
    bool wgen = (g_wnot1 != 0);
    int base = blockIdx.x * SCAN_B;
    int s = 0;
    for (int i = threadIdx.x; i < SCAN_B; i += 256) {
        int idx = base + i;
        if (idx < NN) {
            int c = g_cnt[idx];
            s += c;
            float ws = wgen ? g_dinv[idx] : (float)c;
            g_dinv[idx] = rsqrtf(ws + 1.f);
        }
    }
    sh[threadIdx.x] = s;
    __syncthreads();
    for (int o = 128; o > 0; o >>= 1) {
        if (threadIdx.x < o) sh[threadIdx.x] += sh[threadIdx.x + o];
        __syncthreads();
    }
    if (threadIdx.x == 0) g_bsum[blockIdx.x] = sh[0];
}

// scan pass 2+3 fused
__global__ void scan3_k() {
    __shared__ int bs[128];
    __shared__ int sh[256];
    __shared__ int base_s;
    int tid = threadIdx.x;
    if (tid < 128) bs[tid] = (tid < SCAN_NB) ? g_bsum[tid] : 0;
    __syncthreads();
    for (int o = 1; o < 128; o <<= 1) {
        int v = (tid < 128 && tid >= o) ? bs[tid - o] : 0;
        __syncthreads();
        if (tid < 128) bs[tid] += v;
        __syncthreads();
    }
    if (tid == 0) base_s = bs[blockIdx.x] - g_bsum[blockIdx.x];
    __syncthreads();
    int base = blockIdx.x * SCAN_B;
    int i0 = base + tid * 4;
    int vals[4];
    int tsum = 0;
#pragma unroll
    for (int k = 0; k < 4; k++) {
        int idx = i0 + k;
        vals[k] = (idx < NN) ? g_cnt[idx] : 0;
        tsum += vals[k];
    }
    sh[tid] = tsum;
    __syncthreads();
    for (int o = 1; o < 256; o <<= 1) {
        int v = (tid >= o) ? sh[tid - o] : 0;
        __syncthreads();
        sh[tid] += v;
        __syncthreads();
    }
    int excl = base_s + sh[tid] - tsum;
#pragma unroll
    for (int k = 0; k < 4; k++) {
        int idx = i0 + k;
        if (idx < NN) { g_off[idx] = excl; g_cur[idx] = excl; excl += vals[k]; }
    }
}

// scatter edges into CSR order as packed (row, norm)
__global__ void fill_k(const void* __restrict__ ei, const float* __restrict__ w) {
    long e = (long)blockIdx.x * 256 + threadIdx.x;
    if (e >= NE) return;
    int r, c;
    if (g_is64) {
        const long long* ee = (const long long*)ei;
        r = (int)ee[e]; c = (int)ee[NE + e];
    } else {
        const int* ee = (const int*)ei;
        r = ee[e]; c = ee[NE + e];
    }
    int pos = atomicAdd(&g_cur[c], 1);
    float nrm = g_dinv[r] * w[e] * g_dinv[c];
    g_edge[pos] = make_int2(r, __float_as_int(nrm));
}

// ---------------- layer-1 GEMM: x[N,14] @ W1[14,64] -> fp16 ------------------
__global__ void xw14_k(const float* __restrict__ x, const float* __restrict__ W,
                       __half2* __restrict__ outh) {
    __shared__ float Ws[INF * HID];
    __shared__ float Xs[16][INF];
    int tid = threadIdx.x;  // 256
    for (int i = tid; i < INF * HID; i += 256) Ws[i] = W[i];
    int node0 = blockIdx.x * 16;
    for (int i = tid; i < 16 * INF; i += 256)
        Xs[i / INF][i % INF] = x[(long)(node0 + i / INF) * INF + i % INF];
    __syncthreads();
    int o = tid & 63, ng = tid >> 6;     // 4 groups x 4 nodes
    float acc[4] = {0.f, 0.f, 0.f, 0.f};
#pragma unroll
    for (int k = 0; k < INF; k++) {
        float w = Ws[k * HID + o];
#pragma unroll
        for (int i = 0; i < 4; i++) acc[i] = fmaf(Xs[ng * 4 + i][k], w, acc[i]);
    }
#pragma unroll
    for (int i = 0; i < 4; i++) {
        float hi = __shfl_down_sync(0xffffffffu, acc[i], 1);
        if ((o & 1) == 0)
            outh[(long)(node0 + ng * 4 + i) * 32 + (o >> 1)] = __floats2half2_rn(acc[i], hi);
    }
}

// ------ hidden GEMM: act(h)[N,64] @ W[64,64] -> fp16, BN+ReLU fused in ------
__global__ void xw64_k(const float* __restrict__ x, const float* __restrict__ W,
                       __half2* __restrict__ outh, const float* __restrict__ stats,
                       const float* __restrict__ g, const float* __restrict__ bt) {
    __shared__ float Ws[HID * HID];      // 16 KB
    __shared__ float4 Xs[32][16];        // 8 KB
    __shared__ float As[HID], Cs[HID];
    int tid = threadIdx.x;  // 256
    const float4* W4 = (const float4*)W;
    float4* Ws4 = (float4*)Ws;
    for (int i = tid; i < HID * HID / 4; i += 256) Ws4[i] = W4[i];
    if (tid < HID) {
        float mean = stats[tid] * (1.f / NN);
        float var = stats[64 + tid] * (1.f / NN) - mean * mean;
        float a = g[tid] * rsqrtf(var + EPSV);
        As[tid] = a;
        Cs[tid] = bt[tid] - mean * a;
    }
    __syncthreads();
    int node0 = blockIdx.x * 32;
    const float4* x4 = (const float4*)x;
    for (int i = tid; i < 32 * 16; i += 256) {
        int n = i >> 4, k4 = i & 15;
        float4 v = x4[(long)(node0 + n) * 16 + k4];
        int f = k4 * 4;
        v.x = fmaxf(fmaf(As[f],     v.x, Cs[f]),     0.f);
        v.y = fmaxf(fmaf(As[f + 1], v.y, Cs[f + 1]), 0.f);
        v.z = fmaxf(fmaf(As[f + 2], v.z, Cs[f + 2]), 0.f);
        v.w = fmaxf(fmaf(As[f + 3], v.w, Cs[f + 3]), 0.f);
        Xs[n][k4] = v;
    }
    __syncthreads();
    int o = tid & 63, ng = tid >> 6;     // 4 groups x 8 nodes
    float acc[8] = {0, 0, 0, 0, 0, 0, 0, 0};
#pragma unroll
    for (int k4 = 0; k4 < 16; k4++) {
        float w0 = Ws[(k4 * 4 + 0) * HID + o];
        float w1 = Ws[(k4 * 4 + 1) * HID + o];
        float w2 = Ws[(k4 * 4 + 2) * HID + o];
        float w3 = Ws[(k4 * 4 + 3) * HID + o];
#pragma unroll
        for (int i = 0; i < 8; i++) {
            float4 xv = Xs[ng * 8 + i][k4];
            acc[i] = fmaf(xv.x, w0, fmaf(xv.y, w1, fmaf(xv.z, w2, fmaf(xv.w, w3, acc[i]))));
        }
    }
#pragma unroll
    for (int i = 0; i < 8; i++) {
        float hi = __shfl_down_sync(0xffffffffu, acc[i], 1);
        if ((o & 1) == 0)
            outh[(long)(node0 + ng * 8 + i) * 32 + (o >> 1)] = __floats2half2_rn(acc[i], hi);
    }
}

// ---- CSR gather: 8 lanes/node, fp16 rows (128B), unroll 4 (R7 form) --------
// block 256 = 32 nodes, grid 3125. Fused BN-stats accumulation.
__global__ void gatherh_k(const uint4* __restrict__ xw, float* __restrict__ out,
                          const float* __restrict__ b, float* __restrict__ stats) {
    __shared__ float sm[2 * HID];
    int tid = threadIdx.x;  // 256
    if (tid < 2 * HID) sm[tid] = 0.f;
    __syncthreads();

    int node = blockIdx.x * 32 + (tid >> 3);
    int q = tid & 7;                       // feats [q*8, q*8+8)
    int start = g_off[node], end = g_off[node + 1];
    float d = g_dinv[node];
    float s = d * d;

    float acc[8];
    {
        uint4 sv = xw[(long)node * 8 + q];
        const __half2* h2 = (const __half2*)&sv;
#pragma unroll
        for (int k = 0; k < 4; k++) {
            float2 f = __half22float2(h2[k]);
            acc[2 * k]     = fmaf(s, f.x, b[q * 8 + 2 * k]);
            acc[2 * k + 1] = fmaf(s, f.y, b[q * 8 + 2 * k + 1]);
        }
    }
    int j = start;
    for (; j + 3 < end; j += 4) {
        int2 e0 = g_edge[j], e1 = g_edge[j + 1], e2 = g_edge[j + 2], e3 = g_edge[j + 3];
        uint4 v0 = xw[(long)e0.x * 8 + q];
        uint4 v1 = xw[(long)e1.x * 8 + q];
        uint4 v2 = xw[(long)e2.x * 8 + q];
        uint4 v3 = xw[(long)e3.x * 8 + q];
        float n0 = __int_as_float(e0.y), n1 = __int_as_float(e1.y);
        float n2 = __int_as_float(e2.y), n3 = __int_as_float(e3.y);
        const __half2* a0 = (const __half2*)&v0;
        const __half2* a1 = (const __half2*)&v1;
        const __half2* a2 = (const __half2*)&v2;
        const __half2* a3 = (const __half2*)&v3;
#pragma unroll
        for (int k = 0; k < 4; k++) {
            float2 f0 = __half22float2(a0[k]);
            float2 f1 = __half22float2(a1[k]);
            float2 f2 = __half22float2(a2[k]);
            float2 f3 = __half22float2(a3[k]);
            acc[2 * k]     = fmaf(n0, f0.x, fmaf(n1, f1.x, fmaf(n2, f2.x, fmaf(n3, f3.x, acc[2 * k]))));
            acc[2 * k + 1] = fmaf(n0, f0.y, fmaf(n1, f1.y, fmaf(n2, f2.y, fmaf(n3, f3.y, acc[2 * k + 1]))));
        }
    }
    for (; j < end; j++) {
        int2 e0 = g_edge[j];
        uint4 v0 = xw[(long)e0.x * 8 + q];
        float n0 = __int_as_float(e0.y);
        const __half2* a0 = (const __half2*)&v0;
#pragma unroll
        for (int k = 0; k < 4; k++) {
            float2 f0 = __half22float2(a0[k]);
            acc[2 * k]     = fmaf(n0, f0.x, acc[2 * k]);
            acc[2 * k + 1] = fmaf(n0, f0.y, acc[2 * k + 1]);
        }
    }
    float4* o4 = (float4*)out;
    o4[(long)node * 16 + q * 2]     = make_float4(acc[0], acc[1], acc[2], acc[3]);
    o4[(long)node * 16 + q * 2 + 1] = make_float4(acc[4], acc[5], acc[6], acc[7]);

    // fused BN stats: shfl-reduce across the 4 nodes of this warp, smem, flush
    float ss[8], s2[8];
#pragma unroll
    for (int k = 0; k < 8; k++) { ss[k] = acc[k]; s2[k] = acc[k] * acc[k]; }
#pragma unroll
    for (int off = 8; off < 32; off <<= 1) {
#pragma unroll
        for (int k = 0; k < 8; k++) {
            ss[k] += __shfl_xor_sync(0xffffffffu, ss[k], off);
            s2[k] += __shfl_xor_sync(0xffffffffu, s2[k], off);
        }
    }
    if ((tid & 31) < 8) {
#pragma unroll
        for (int k = 0; k < 8; k++) {
            atomicAdd(&sm[q * 8 + k], ss[k]);
            atomicAdd(&sm[64 + q * 8 + k], s2[k]);
        }
    }
    __syncthreads();
    if (tid < 2 * HID) atomicAdd(&stats[tid], sm[tid]);
}

// ---------------- bn+relu apply -> node_out (streaming, no atomics) ---------
__global__ void bnrelu_node_k(const float4* __restrict__ h, float4* __restrict__ no,
                              const float* __restrict__ stats,
                              const float* __restrict__ g, const float* __restrict__ bt) {
    __shared__ float As[HID], Cs[HID];
    int tid = threadIdx.x;
    if (tid < HID) {
        float mean = stats[tid] * (1.f / NN);
        float var = stats[64 + tid] * (1.f / NN) - mean * mean;
        float a = g[tid] * rsqrtf(var + EPSV);
        As[tid] = a;
        Cs[tid] = bt[tid] - mean * a;
    }
    __syncthreads();
    long t = (long)blockIdx.x * 256 + tid;
    if (t >= (long)NN * 16) return;
    int q = (int)(t & 15);
    int f0 = q * 4;
    float4 v = h[t];
    v.x = fmaxf(fmaf(As[f0],     v.x, Cs[f0]),     0.f);
    v.y = fmaxf(fmaf(As[f0 + 1], v.y, Cs[f0 + 1]), 0.f);
    v.z = fmaxf(fmaf(As[f0 + 2], v.z, Cs[f0 + 2]), 0.f);
    v.w = fmaxf(fmaf(As[f0 + 3], v.w, Cs[f0 + 3]), 0.f);
    no[t] = v;
}

// ------- per-graph pooling + FC: 256 thr/graph (4 node-rows in flight) ------
__global__ void poolfc_k(const float* __restrict__ no, float* __restrict__ gemb,
                         const float* __restrict__ W, const float* __restrict__ b,
                         float* __restrict__ out) {
    __shared__ int sb[2];
    __shared__ float sm[256];
    __shared__ float red[4];
    int gr = blockIdx.x;
    int tid = threadIdx.x;  // 256
    int f = tid & 63, sub = tid >> 6;    // 4 subs x 64 feats
    if (tid < 2) {
        int target = gr + tid;
        int lo = 0, hi = NN;
        while (lo < hi) {
            int mid = (lo + hi) >> 1;
            if (g_batch[mid] < target) lo = mid + 1; else hi = mid;
        }
        sb[tid] = lo;
    }
    __syncthreads();
    int start = sb[0], end = sb[1];
    float acc = 0.f;
    for (int n = start + sub; n < end; n += 4)
        acc += no[(long)n * HID + f];
    sm[tid] = acc;
    __syncthreads();
    if (tid < HID) {
        float a = sm[tid] + sm[64 + tid] + sm[128 + tid] + sm[192 + tid];
        gemb[(long)gr * HID + tid] = a;
        float p0 = a * W[tid * 2];
        float p1 = a * W[tid * 2 + 1];
#pragma unroll
        for (int o = 16; o > 0; o >>= 1) {
            p0 += __shfl_down_sync(0xffffffffu, p0, o);
            p1 += __shfl_down_sync(0xffffffffu, p1, o);
        }
        if ((tid & 31) == 0) { red[(tid >> 5) * 2] = p0; red[(tid >> 5) * 2 + 1] = p1; }
    }
    __syncthreads();
    if (tid == 0) {
        out[gr * 2]     = red[0] + red[2] + b[0];
        out[gr * 2 + 1] = red[1] + red[3] + b[1];
    }
}

// ---------------- orchestration ----------------------------------------------
extern "C" void kernel_launch(void* const* d_in, const int* in_sizes, int n_in,
                              void* d_out, int out_size) {
    const float* x  = (const float*)d_in[0];
    const void*  ei = d_in[1];
    const void*  bt = d_in[2];
    const float* ew = (const float*)d_in[3];
    const float* W1 = (const float*)d_in[4];
    const float* b1 = (const float*)d_in[5];
    const float* W2 = (const float*)d_in[6];
    const float* b2 = (const float*)d_in[7];
    const float* W3 = (const float*)d_in[8];
    const float* b3 = (const float*)d_in[9];
    const float* g1 = (const float*)d_in[10];
    const float* t1 = (const float*)d_in[11];
    const float* g2 = (const float*)d_in[12];
    const float* t2 = (const float*)d_in[13];
    const float* g3 = (const float*)d_in[14];
    const float* t3 = (const float*)d_in[15];
    const float* fcW = (const float*)d_in[16];
    const float* fcb = (const float*)d_in[17];

    float* out      = (float*)d_out;
    float* node_out = out + NG * 2;
    float* gemb     = node_out + (long)NN * HID;

    __half2* A;
    float *B, *S;
    cudaGetSymbolAddress((void**)&A, g_Ah);
    cudaGetSymbolAddress((void**)&B, g_B);
    cudaGetSymbolAddress((void**)&S, g_stats);

    const int NB_N   = (NN + 255) / 256;                    // 391
    const int NB_E   = (NE + 255) / 256;                    // 6250
    const int NB_NF4 = (int)(((long)NN * 16 + 255) / 256);  // 6250

    // ---- CSR build (once, reused by all 3 layers)
    init_k<<<NB_N, 256>>>((const int*)ei, ew);
    convert_hist_k<<<2048, 256>>>(ei, bt, ew);
    scan1_k<<<SCAN_NB, 256>>>();
    scan3_k<<<SCAN_NB, 256>>>();
    fill_k<<<NB_E, 256>>>(ei, ew);

    // ---- layer 1
    xw14_k<<<NN / 16, 256>>>(x, W1, A);
    gatherh_k<<<NN / 32, 256>>>((const uint4*)A, B, b1, S);

    // ---- layer 2 (BN+ReLU of layer 1 folded into GEMM input)
    xw64_k<<<NN / 32, 256>>>(B, W2, A, S, g1, t1);
    gatherh_k<<<NN / 32, 256>>>((const uint4*)A, B, b2, S + 128);

    // ---- layer 3
    xw64_k<<<NN / 32, 256>>>(B, W3, A, S + 128, g2, t2);
    gatherh_k<<<NN / 32, 256>>>((const uint4*)A, B, b3, S + 256);

    // ---- bn+relu -> node_out, per-graph pool + fc
    bnrelu_node_k<<<NB_NF4, 256>>>((const float4*)B, (float4*)node_out, S + 256, g3, t3);
    poolfc_k<<<NG, 256>>>(node_out, gemb, fcW, fcb, out);
}

// round 16
// speedup vs baseline: 1.0174x; 1.0028x over previous
#include <cuda_runtime.h>
#include <cuda_fp16.h>

#define NN 100000
#define NE 1600000
#define NG 2048
#define HID 64
#define INF 14
#define EPSV 1e-5f
#define SCAN_B 1024
#define SCAN_NB ((NN + SCAN_B - 1) / SCAN_B)   // 98

// ---------------- scratch (device globals; no allocation allowed) -----------
__device__ __half2 g_Ah[NN * 32];      // 12.8 MB xw buffer (fp16)
__device__ float   g_B[NN * HID];      // 25.6 MB h buffer (fp32)
__device__ float   g_dinv[NN];
__device__ float   g_stats[3][2 * HID];
__device__ int2    g_edge[NE];         // CSR-sorted (row, norm-bits)
__device__ int     g_cnt[NN];
__device__ int     g_off[NN + 1];
__device__ int     g_cur[NN];
__device__ int     g_bsum[SCAN_NB];
__device__ int     g_batch[NN];
__device__ int     g_is64;
// monotone flag: 0 (static zero-init) until any edge_weight != 1.0f is seen.
__device__ int     g_wnot1;

// ---------------- init: zero + dtype detection + weight==1 check -------------
__global__ void init_k(const int* __restrict__ ei32, const float* __restrict__ w) {
    int i = blockIdx.x * blockDim.x + threadIdx.x;
    if (i < NN) { g_cnt[i] = 0; g_dinv[i] = 0.f; }
    if (i < 3 * 2 * HID) ((float*)g_stats)[i] = 0.f;
    if (i == 0) g_off[NN] = NE;
    int nt = gridDim.x * blockDim.x;
    int bad = 0;
    for (long e = i; e < NE; e += nt)
        if (w[e] != 1.0f) bad = 1;
    if (__syncthreads_or(bad) && threadIdx.x == 0) atomicOr(&g_wnot1, 1);
    if (blockIdx.x == 0) {
        __shared__ int any;
        if (threadIdx.x == 0) any = 0;
        __syncthreads();
        for (int s = 0; s < 8; s++) {
            long idx = 1 + 2L * (threadIdx.x * 8 + s) * 780;
            if (idx < 2L * NE && ei32[idx] != 0) any = 1;
        }
        __syncthreads();
        if (threadIdx.x == 0) g_is64 = (any == 0) ? 1 : 0;
    }
}

// histogram + batch conversion. Fast path: weights all 1 -> only int atomic.
__global__ void convert_hist_k(const void* __restrict__ ei, const void* __restrict__ bt,
                               const float* __restrict__ w) {
    long t0 = (long)blockIdx.x * blockDim.x + threadIdx.x;
    long stride = (long)gridDim.x * blockDim.x;
    bool wgen = (g_wnot1 != 0);
    if (g_is64) {
        const long long* e = (const long long*)ei;
        const long long* b = (const long long*)bt;
        for (long i = t0; i < NE; i += stride) {
            int c = (int)e[NE + i];
            atomicAdd(&g_cnt[c], 1);
            if (wgen) atomicAdd(&g_dinv[c], w[i]);
        }
        for (long i = t0; i < NN; i += stride) g_batch[i] = (int)b[i];
    } else {
        const int* e = (const int*)ei;
        const int* b = (const int*)bt;
        for (long i = t0; i < NE; i += stride) {
            int c = e[NE + i];
            atomicAdd(&g_cnt[c], 1);
            if (wgen) atomicAdd(&g_dinv[c], w[i]);
        }
        for (long i = t0; i < NN; i += stride) g_batch[i] = b[i];
    }
}

// ---------------- scan pass 1 (block sums) + fused dinv ----------------------
__global__ void scan1_k() {
    __shared__ int sh[256];
    bool wgen = (g_wnot1 != 0);
    int base = blockIdx.x * SCAN_B;
    int s = 0;
    for (int i = threadIdx.x; i < SCAN_B; i += 256) {
        int idx = base + i;
        if (idx < NN) {
            int c = g_cnt[idx];
            s += c;
            float ws = wgen ? g_dinv[idx] : (float)c;
            g_dinv[idx] = rsqrtf(ws + 1.f);
        }
    }
    sh[threadIdx.x] = s;
    __syncthreads();
    for (int o = 128; o > 0; o >>= 1) {
        if (threadIdx.x < o) sh[threadIdx.x] += sh[threadIdx.x + o];
        __syncthreads();
    }
    if (threadIdx.x == 0) g_bsum[blockIdx.x] = sh[0];
}

// scan pass 2+3 fused
__global__ void scan3_k() {
    __shared__ int bs[128];
    __shared__ int sh[256];
    __shared__ int base_s;
    int tid = threadIdx.x;
    if (tid < 128) bs[tid] = (tid < SCAN_NB) ? g_bsum[tid] : 0;
    __syncthreads();
    for (int o = 1; o < 128; o <<= 1) {
        int v = (tid < 128 && tid >= o) ? bs[tid - o] : 0;
        __syncthreads();
        if (tid < 128) bs[tid] += v;
        __syncthreads();
    }
    if (tid == 0) base_s = bs[blockIdx.x] - g_bsum[blockIdx.x];
    __syncthreads();
    int base = blockIdx.x * SCAN_B;
    int i0 = base + tid * 4;
    int vals[4];
    int tsum = 0;
#pragma unroll
    for (int k = 0; k < 4; k++) {
        int idx = i0 + k;
        vals[k] = (idx < NN) ? g_cnt[idx] : 0;
        tsum += vals[k];
    }
    sh[tid] = tsum;
    __syncthreads();
    for (int o = 1; o < 256; o <<= 1) {
        int v = (tid >= o) ? sh[tid - o] : 0;
        __syncthreads();
        sh[tid] += v;
        __syncthreads();
    }
    int excl = base_s + sh[tid] - tsum;
#pragma unroll
    for (int k = 0; k < 4; k++) {
        int idx = i0 + k;
        if (idx < NN) { g_off[idx] = excl; g_cur[idx] = excl; excl += vals[k]; }
    }
}

// scatter edges into CSR order as packed (row, norm)
__global__ void fill_k(const void* __restrict__ ei, const float* __restrict__ w) {
    long e = (long)blockIdx.x * 256 + threadIdx.x;
    if (e >= NE) return;
    int r, c;
    if (g_is64) {
        const long long* ee = (const long long*)ei;
        r = (int)ee[e]; c = (int)ee[NE + e];
    } else {
        const int* ee = (const int*)ei;
        r = ee[e]; c = ee[NE + e];
    }
    int pos = atomicAdd(&g_cur[c], 1);
    float nrm = g_dinv[r] * w[e] * g_dinv[c];
    g_edge[pos] = make_int2(r, __float_as_int(nrm));
}

// ---------------- layer-1 GEMM: x[N,14] @ W1[14,64] -> fp16 ------------------
__global__ void xw14_k(const float* __restrict__ x, const float* __restrict__ W,
                       __half2* __restrict__ outh) {
    __shared__ float Ws[INF * HID];
    __shared__ float Xs[16][INF];
    int tid = threadIdx.x;  // 256
    for (int i = tid; i < INF * HID; i += 256) Ws[i] = W[i];
    int node0 = blockIdx.x * 16;
    for (int i = tid; i < 16 * INF; i += 256)
        Xs[i / INF][i % INF] = x[(long)(node0 + i / INF) * INF + i % INF];
    __syncthreads();
    int o = tid & 63, ng = tid >> 6;     // 4 groups x 4 nodes
    float acc[4] = {0.f, 0.f, 0.f, 0.f};
#pragma unroll
    for (int k = 0; k < INF; k++) {
        float w = Ws[k * HID + o];
#pragma unroll
        for (int i = 0; i < 4; i++) acc[i] = fmaf(Xs[ng * 4 + i][k], w, acc[i]);
    }
#pragma unroll
    for (int i = 0; i < 4; i++) {
        float hi = __shfl_down_sync(0xffffffffu, acc[i], 1);
        if ((o & 1) == 0)
            outh[(long)(node0 + ng * 4 + i) * 32 + (o >> 1)] = __floats2half2_rn(acc[i], hi);
    }
}

// ------ hidden GEMM: act(h)[N,64] @ W[64,64] -> fp16, BN+ReLU fused in ------
__global__ void xw64_k(const float* __restrict__ x, const float* __restrict__ W,
                       __half2* __restrict__ outh, const float* __restrict__ stats,
                       const float* __restrict__ g, const float* __restrict__ bt) {
    __shared__ float Ws[HID * HID];      // 16 KB
    __shared__ float4 Xs[32][16];        // 8 KB
    __shared__ float As[HID], Cs[HID];
    int tid = threadIdx.x;  // 256
    const float4* W4 = (const float4*)W;
    float4* Ws4 = (float4*)Ws;
    for (int i = tid; i < HID * HID / 4; i += 256) Ws4[i] = W4[i];
    if (tid < HID) {
        float mean = stats[tid] * (1.f / NN);
        float var = stats[64 + tid] * (1.f / NN) - mean * mean;
        float a = g[tid] * rsqrtf(var + EPSV);
        As[tid] = a;
        Cs[tid] = bt[tid] - mean * a;
    }
    __syncthreads();
    int node0 = blockIdx.x * 32;
    const float4* x4 = (const float4*)x;
    for (int i = tid; i < 32 * 16; i += 256) {
        int n = i >> 4, k4 = i & 15;
        float4 v = x4[(long)(node0 + n) * 16 + k4];
        int f = k4 * 4;
        v.x = fmaxf(fmaf(As[f],     v.x, Cs[f]),     0.f);
        v.y = fmaxf(fmaf(As[f + 1], v.y, Cs[f + 1]), 0.f);
        v.z = fmaxf(fmaf(As[f + 2], v.z, Cs[f + 2]), 0.f);
        v.w = fmaxf(fmaf(As[f + 3], v.w, Cs[f + 3]), 0.f);
        Xs[n][k4] = v;
    }
    __syncthreads();
    int o = tid & 63, ng = tid >> 6;     // 4 groups x 8 nodes
    float acc[8] = {0, 0, 0, 0, 0, 0, 0, 0};
#pragma unroll
    for (int k4 = 0; k4 < 16; k4++) {
        float w0 = Ws[(k4 * 4 + 0) * HID + o];
        float w1 = Ws[(k4 * 4 + 1) * HID + o];
        float w2 = Ws[(k4 * 4 + 2) * HID + o];
        float w3 = Ws[(k4 * 4 + 3) * HID + o];
#pragma unroll
        for (int i = 0; i < 8; i++) {
            float4 xv = Xs[ng * 8 + i][k4];
            acc[i] = fmaf(xv.x, w0, fmaf(xv.y, w1, fmaf(xv.z, w2, fmaf(xv.w, w3, acc[i]))));
        }
    }
#pragma unroll
    for (int i = 0; i < 8; i++) {
        float hi = __shfl_down_sync(0xffffffffu, acc[i], 1);
        if ((o & 1) == 0)
            outh[(long)(node0 + ng * 8 + i) * 32 + (o >> 1)] = __floats2half2_rn(acc[i], hi);
    }
}

// ---- CSR gather: 8 lanes/node, fp16 rows (128B), unroll 4 (R7 form) --------
__global__ void gatherh_k(const uint4* __restrict__ xw, float* __restrict__ out,
                          const float* __restrict__ b, float* __restrict__ stats) {
    __shared__ float sm[2 * HID];
    int tid = threadIdx.x;  // 256
    if (tid < 2 * HID) sm[tid] = 0.f;
    __syncthreads();

    int node = blockIdx.x * 32 + (tid >> 3);
    int q = tid & 7;                       // feats [q*8, q*8+8)
    int start = g_off[node], end = g_off[node + 1];
    float d = g_dinv[node];
    float s = d * d;

    float acc[8];
    {
        uint4 sv = xw[(long)node * 8 + q];
        const __half2* h2 = (const __half2*)&sv;
#pragma unroll
        for (int k = 0; k < 4; k++) {
            float2 f = __half22float2(h2[k]);
            acc[2 * k]     = fmaf(s, f.x, b[q * 8 + 2 * k]);
            acc[2 * k + 1] = fmaf(s, f.y, b[q * 8 + 2 * k + 1]);
        }
    }
    int j = start;
    for (; j + 3 < end; j += 4) {
        int2 e0 = g_edge[j], e1 = g_edge[j + 1], e2 = g_edge[j + 2], e3 = g_edge[j + 3];
        uint4 v0 = xw[(long)e0.x * 8 + q];
        uint4 v1 = xw[(long)e1.x * 8 + q];
        uint4 v2 = xw[(long)e2.x * 8 + q];
        uint4 v3 = xw[(long)e3.x * 8 + q];
        float n0 = __int_as_float(e0.y), n1 = __int_as_float(e1.y);
        float n2 = __int_as_float(e2.y), n3 = __int_as_float(e3.y);
        const __half2* a0 = (const __half2*)&v0;
        const __half2* a1 = (const __half2*)&v1;
        const __half2* a2 = (const __half2*)&v2;
        const __half2* a3 = (const __half2*)&v3;
#pragma unroll
        for (int k = 0; k < 4; k++) {
            float2 f0 = __half22float2(a0[k]);
            float2 f1 = __half22float2(a1[k]);
            float2 f2 = __half22float2(a2[k]);
            float2 f3 = __half22float2(a3[k]);
            acc[2 * k]     = fmaf(n0, f0.x, fmaf(n1, f1.x, fmaf(n2, f2.x, fmaf(n3, f3.x, acc[2 * k]))));
            acc[2 * k + 1] = fmaf(n0, f0.y, fmaf(n1, f1.y, fmaf(n2, f2.y, fmaf(n3, f3.y, acc[2 * k + 1]))));
        }
    }
    for (; j < end; j++) {
        int2 e0 = g_edge[j];
        uint4 v0 = xw[(long)e0.x * 8 + q];
        float n0 = __int_as_float(e0.y);
        const __half2* a0 = (const __half2*)&v0;
#pragma unroll
        for (int k = 0; k < 4; k++) {
            float2 f0 = __half22float2(a0[k]);
            acc[2 * k]     = fmaf(n0, f0.x, acc[2 * k]);
            acc[2 * k + 1] = fmaf(n0, f0.y, acc[2 * k + 1]);
        }
    }
    float4* o4 = (float4*)out;
    o4[(long)node * 16 + q * 2]     = make_float4(acc[0], acc[1], acc[2], acc[3]);
    o4[(long)node * 16 + q * 2 + 1] = make_float4(acc[4], acc[5], acc[6], acc[7]);

    float ss[8], s2[8];
#pragma unroll
    for (int k = 0; k < 8; k++) { ss[k] = acc[k]; s2[k] = acc[k] * acc[k]; }
#pragma unroll
    for (int off = 8; off < 32; off <<= 1) {
#pragma unroll
        for (int k = 0; k < 8; k++) {
            ss[k] += __shfl_xor_sync(0xffffffffu, ss[k], off);
            s2[k] += __shfl_xor_sync(0xffffffffu, s2[k], off);
        }
    }
    if ((tid & 31) < 8) {
#pragma unroll
        for (int k = 0; k < 8; k++) {
            atomicAdd(&sm[q * 8 + k], ss[k]);
            atomicAdd(&sm[64 + q * 8 + k], s2[k]);
        }
    }
    __syncthreads();
    if (tid < 2 * HID) atomicAdd(&stats[tid], sm[tid]);
}

// ---------------- bn+relu apply -> node_out (streaming, no atomics) ---------
__global__ void bnrelu_node_k(const float4* __restrict__ h, float4* __restrict__ no,
                              const float* __restrict__ stats,
                              const float* __restrict__ g, const float* __restrict__ bt) {
    __shared__ float As[HID], Cs[HID];
    int tid = threadIdx.x;
    if (tid < HID) {
        float mean = stats[tid] * (1.f / NN);
        float var = stats[64 + tid] * (1.f / NN) - mean * mean;
        float a = g[tid] * rsqrtf(var + EPSV);
        As[tid] = a;
        Cs[tid] = bt[tid] - mean * a;
    }
    __syncthreads();
    long t = (long)blockIdx.x * 256 + tid;
    if (t >= (long)NN * 16) return;
    int q = (int)(t & 15);
    int f0 = q * 4;
    float4 v = h[t];
    v.x = fmaxf(fmaf(As[f0],     v.x, Cs[f0]),     0.f);
    v.y = fmaxf(fmaf(As[f0 + 1], v.y, Cs[f0 + 1]), 0.f);
    v.z = fmaxf(fmaf(As[f0 + 2], v.z, Cs[f0 + 2]), 0.f);
    v.w = fmaxf(fmaf(As[f0 + 3], v.w, Cs[f0 + 3]), 0.f);
    no[t] = v;
}

// ------- per-graph pooling + FC: 256 thr/graph (4 node-rows in flight) ------
__global__ void poolfc_k(const float* __restrict__ no, float* __restrict__ gemb,
                         const float* __restrict__ W, const float* __restrict__ b,
                         float* __restrict__ out) {
    __shared__ int sb[2];
    __shared__ float sm[256];
    __shared__ float red[4];
    int gr = blockIdx.x;
    int tid = threadIdx.x;  // 256
    int f = tid & 63, sub = tid >> 6;    // 4 subs x 64 feats
    if (tid < 2) {
        int target = gr + tid;
        int lo = 0, hi = NN;
        while (lo < hi) {
            int mid = (lo + hi) >> 1;
            if (g_batch[mid] < target) lo = mid + 1; else hi = mid;
        }
        sb[tid] = lo;
    }
    __syncthreads();
    int start = sb[0], end = sb[1];
    float acc = 0.f;
    for (int n = start + sub; n < end; n += 4)
        acc += no[(long)n * HID + f];
    sm[tid] = acc;
    __syncthreads();
    if (tid < HID) {
        float a = sm[tid] + sm[64 + tid] + sm[128 + tid] + sm[192 + tid];
        gemb[(long)gr * HID + tid] = a;
        float p0 = a * W[tid * 2];
        float p1 = a * W[tid * 2 + 1];
#pragma unroll
        for (int o = 16; o > 0; o >>= 1) {
            p0 += __shfl_down_sync(0xffffffffu, p0, o);
            p1 += __shfl_down_sync(0xffffffffu, p1, o);
        }
        if ((tid & 31) == 0) { red[(tid >> 5) * 2] = p0; red[(tid >> 5) * 2 + 1] = p1; }
    }
    __syncthreads();
    if (tid == 0) {
        out[gr * 2]     = red[0] + red[2] + b[0];
        out[gr * 2 + 1] = red[1] + red[3] + b[1];
    }
}

// ---------------- orchestration ----------------------------------------------
extern "C" void kernel_launch(void* const* d_in, const int* in_sizes, int n_in,
                              void* d_out, int out_size) {
    const float* x  = (const float*)d_in[0];
    const void*  ei = d_in[1];
    const void*  bt = d_in[2];
    const float* ew = (const float*)d_in[3];
    const float* W1 = (const float*)d_in[4];
    const float* b1 = (const float*)d_in[5];
    const float* W2 = (const float*)d_in[6];
    const float* b2 = (const float*)d_in[7];
    const float* W3 = (const float*)d_in[8];
    const float* b3 = (const float*)d_in[9];
    const float* g1 = (const float*)d_in[10];
    const float* t1 = (const float*)d_in[11];
    const float* g2 = (const float*)d_in[12];
    const float* t2 = (const float*)d_in[13];
    const float* g3 = (const float*)d_in[14];
    const float* t3 = (const float*)d_in[15];
    const float* fcW = (const float*)d_in[16];
    const float* fcb = (const float*)d_in[17];

    float* out      = (float*)d_out;
    float* node_out = out + NG * 2;
    float* gemb     = node_out + (long)NN * HID;

    __half2* A;
    float *B, *S;
    cudaGetSymbolAddress((void**)&A, g_Ah);
    cudaGetSymbolAddress((void**)&B, g_B);
    cudaGetSymbolAddress((void**)&S, g_stats);

    const int NB_N   = (NN + 255) / 256;                    // 391
    const int NB_E   = (NE + 255) / 256;                    // 6250
    const int NB_NF4 = (int)(((long)NN * 16 + 255) / 256);  // 6250

    // One-time host objects (created on the non-captured correctness call;
    // the capture call performs only capturable record/wait operations).
    static cudaStream_t s_aux = nullptr;
    static cudaEvent_t  s_fork = nullptr, s_join = nullptr;
    static bool s_tried = false;
    if (!s_tried) {
        s_tried = true;
        if (cudaStreamCreateWithFlags(&s_aux, cudaStreamNonBlocking) == cudaSuccess) {
            if (cudaEventCreateWithFlags(&s_fork, cudaEventDisableTiming) != cudaSuccess ||
                cudaEventCreateWithFlags(&s_join, cudaEventDisableTiming) != cudaSuccess) {
                s_aux = nullptr;
            }
        } else {
            s_aux = nullptr;
        }
    }

    if (s_aux) {
        // fork: xw14 (independent of CSR) runs concurrently with the CSR build
        cudaEventRecord(s_fork, 0);
        cudaStreamWaitEvent(s_aux, s_fork, 0);
        xw14_k<<<NN / 16, 256, 0, s_aux>>>(x, W1, A);
        cudaEventRecord(s_join, s_aux);
    }

    // ---- CSR build (once, reused by all 3 layers)
    init_k<<<NB_N, 256>>>((const int*)ei, ew);
    convert_hist_k<<<2048, 256>>>(ei, bt, ew);
    scan1_k<<<SCAN_NB, 256>>>();
    scan3_k<<<SCAN_NB, 256>>>();
    fill_k<<<NB_E, 256>>>(ei, ew);

    if (s_aux) {
        cudaStreamWaitEvent(0, s_join, 0);
    } else {
        xw14_k<<<NN / 16, 256>>>(x, W1, A);
    }

    // ---- layer 1
    gatherh_k<<<NN / 32, 256>>>((const uint4*)A, B, b1, S);

    // ---- layer 2 (BN+ReLU of layer 1 folded into GEMM input)
    xw64_k<<<NN / 32, 256>>>(B, W2, A, S, g1, t1);
    gatherh_k<<<NN / 32, 256>>>((const uint4*)A, B, b2, S + 128);

    // ---- layer 3
    xw64_k<<<NN / 32, 256>>>(B, W3, A, S + 128, g2, t2);
    gatherh_k<<<NN / 32, 256>>>((const uint4*)A, B, b3, S + 256);

    // ---- bn+relu -> node_out, per-graph pool + fc
    bnrelu_node_k<<<NB_NF4, 256>>>((const float4*)B, (float4*)node_out, S + 256, g3, t3);
    poolfc_k<<<NG, 256>>>(node_out, gemb, fcW, fcb, out);
}